// round 1
// baseline (speedup 1.0000x reference)
#include <cuda_runtime.h>
#include <math_constants.h>

// Problem constants (from reference setup_inputs)
#define NS   5
#define NC   64
#define NB   8
#define HIN  512
#define WIN  512
#define HO   257
#define WO   257
#define NPIX (HO*WO)   // 66049

// Precomputed piecewise-linear tables (per scale):
//   P[o](L) = max( S1[o,k] + S2[o,k]*L , 0 )   where k = #{sorted thresholds < L}
__device__ float  g_tab[NS][NC][65][2];   // [s][o][k][{S1,S2}]  ~166 KB
__device__ float  g_th [NS][64];          // sorted thresholds
__device__ float  g_wv [NS][4];           // lp0,lp1,hp0,hp1

// ---------------------------------------------------------------------------
// Kernel 1: build tables. 5 blocks (one per scale), 64 threads.
// Done in double precision so the running prefix/suffix sums introduce no
// meaningful error vs. the reference's direct summation.
// ---------------------------------------------------------------------------
__global__ void precompute_kernel(
    const float* __restrict__ lp, const float* __restrict__ hp,
    const float* __restrict__ w1, const float* __restrict__ w2,
    const float* __restrict__ g1, const float* __restrict__ b1,
    const float* __restrict__ m1, const float* __restrict__ v1,
    const float* __restrict__ g2, const float* __restrict__ b2,
    const float* __restrict__ m2, const float* __restrict__ v2)
{
    const int s = blockIdx.x;
    const int c = threadIdx.x;          // channel (phase 1) / output channel (phase 2)

    __shared__ double sA[64], sB[64];
    __shared__ float  sth[64];
    __shared__ int    sidx[64];

    // phase 1: per hidden channel c: t_c(L) = relu(A*L + B)
    {
        double sc1 = (double)g1[s*NC + c] / sqrt((double)v1[s*NC + c] + 1e-5);
        double sh1 = (double)b1[s*NC + c] - (double)m1[s*NC + c] * sc1;
        double A   = (double)w1[s*NC + c] * sc1;
        sA[c] = A; sB[c] = sh1;
        sth[c] = (A != 0.0) ? (float)(-sh1 / A) : CUDART_INF_F;
        sidx[c] = c;
    }
    __syncthreads();

    // sort thresholds (single thread, 64 elems — trivial)
    if (c == 0) {
        for (int i = 1; i < 64; i++) {
            float tv = sth[i]; int ti = sidx[i]; int j = i - 1;
            while (j >= 0 && sth[j] > tv) { sth[j+1] = sth[j]; sidx[j+1] = sidx[j]; j--; }
            sth[j+1] = tv; sidx[j+1] = ti;
        }
        for (int i = 0; i < 64; i++) g_th[s][i] = sth[i];
        g_wv[s][0] = lp[s*2]; g_wv[s][1] = lp[s*2+1];
        g_wv[s][2] = hp[s*2]; g_wv[s][3] = hp[s*2+1];
    }
    __syncthreads();

    // phase 2: thread = output channel o; build S1/S2 over rank k
    const int o = c;
    double sc2 = (double)g2[s*NC + o] / sqrt((double)v2[s*NC + o] + 1e-5);
    double sh2 = (double)b2[s*NC + o] - (double)m2[s*NC + o] * sc2;

    // k = 0 active set: {A<0 : all}  plus constant channels {A==0 && B>0}
    double s1 = 0.0, s2 = 0.0;
    for (int cc = 0; cc < 64; cc++) {
        double w = (double)w2[(s*NC + o)*NC + cc];
        double a = sA[cc], bb = sB[cc];
        if (a < 0.0)                      { s1 += w*bb; s2 += w*a; }
        else if (a == 0.0 && bb > 0.0)    { s1 += w*bb; }
    }
    for (int k = 0; k <= 64; k++) {
        g_tab[s][o][k][0] = (float)(sc2*s1 + sh2);
        g_tab[s][o][k][1] = (float)(sc2*s2);
        if (k < 64) {
            int cc = sidx[k];
            double w = (double)w2[(s*NC + o)*NC + cc];
            double a = sA[cc], bb = sB[cc];
            if (a > 0.0)      { s1 += w*bb; s2 += w*a; }   // channel turns ON
            else if (a < 0.0) { s1 -= w*bb; s2 -= w*a; }   // channel turns OFF
        }
    }
}

// ---------------------------------------------------------------------------
// Kernel 2: main. One thread per output pixel (grid-stride).
// Output layout assumed: [ L(S,B,1,257,257) | Hc(same) | P(S,B,64,257,257) ]
// ---------------------------------------------------------------------------
__global__ void __launch_bounds__(256)
dwt_pwl_kernel(const float* __restrict__ x, float* __restrict__ out)
{
    __shared__ float2 stab[64*65];   // 33280 B
    __shared__ float  sth[64];

    const int s = blockIdx.y / NB;
    const int b = blockIdx.y % NB;

    // cooperative table load (L2-resident after first wave)
    const float2* gt = reinterpret_cast<const float2*>(&g_tab[s][0][0][0]);
    for (int i = threadIdx.x; i < 64*65; i += 256) stab[i] = gt[i];
    if (threadIdx.x < 64) sth[threadIdx.x] = g_th[s][threadIdx.x];
    const float lp0 = g_wv[s][0], lp1 = g_wv[s][1];
    const float hp0 = g_wv[s][2], hp1 = g_wv[s][3];
    __syncthreads();

    const float* __restrict__ xb = x + (size_t)b * HIN * WIN;
    float* __restrict__ outL = out + (size_t)(s*NB + b) * NPIX;
    float* __restrict__ outH = out + (size_t)(NS*NB + s*NB + b) * NPIX;
    float* __restrict__ outP = out + (size_t)2*NS*NB*NPIX
                                   + (size_t)(s*NB + b) * NC * NPIX;

    for (int pix = blockIdx.x * 256 + threadIdx.x; pix < NPIX;
         pix += gridDim.x * 256)
    {
        const int i = pix / WO;
        const int j = pix - i * WO;
        const int r0 = 2*i - 1, r1 = 2*i;
        const int c0 = 2*j - 1, c1 = 2*j;

        // zero-padded 2x2 stencil
        const float x00 = (r0 >= 0   && c0 >= 0 ) ? xb[r0*WIN + c0] : 0.f;
        const float x01 = (r0 >= 0   && c1 < WIN) ? xb[r0*WIN + c1] : 0.f;
        const float x10 = (r1 < HIN  && c0 >= 0 ) ? xb[r1*WIN + c0] : 0.f;
        const float x11 = (r1 < HIN  && c1 < WIN) ? xb[r1*WIN + c1] : 0.f;

        const float L  = lp0*(lp0*x00 + lp1*x01) + lp1*(lp0*x10 + lp1*x11);
        const float Hc = hp0*(hp0*x00 + hp1*x01) + hp1*(hp0*x10 + hp1*x11);
        outL[pix] = L;
        outH[pix] = Hc;

        // branchless rank: k = #{th < L}, k in [0,64]
        int k = (sth[31]      < L) ? 32 : 0;
        k += (sth[k + 15] < L) ? 16 : 0;
        k += (sth[k +  7] < L) ?  8 : 0;
        k += (sth[k +  3] < L) ?  4 : 0;
        k += (sth[k +  1] < L) ?  2 : 0;
        k += (sth[k     ] < L) ?  1 : 0;

        #pragma unroll 8
        for (int o = 0; o < 64; o++) {
            const float2 f = stab[o*65 + k];
            outP[(size_t)o * NPIX + pix] = fmaxf(fmaf(f.y, L, f.x), 0.f);
        }
    }
}

// ---------------------------------------------------------------------------
extern "C" void kernel_launch(void* const* d_in, const int* in_sizes, int n_in,
                              void* d_out, int out_size)
{
    const float* x  = (const float*)d_in[0];
    const float* lp = (const float*)d_in[1];
    const float* hp = (const float*)d_in[2];
    const float* w1 = (const float*)d_in[3];
    const float* w2 = (const float*)d_in[4];
    const float* g1 = (const float*)d_in[5];
    const float* b1 = (const float*)d_in[6];
    const float* m1 = (const float*)d_in[7];
    const float* v1 = (const float*)d_in[8];
    const float* g2 = (const float*)d_in[9];
    const float* b2 = (const float*)d_in[10];
    const float* m2 = (const float*)d_in[11];
    const float* v2 = (const float*)d_in[12];
    float* out = (float*)d_out;

    precompute_kernel<<<NS, 64>>>(lp, hp, w1, w2, g1, b1, m1, v1,
                                  g2, b2, m2, v2);

    dim3 grid(30, NS * NB);   // 1200 blocks, ~9 pixel-iters each
    dwt_pwl_kernel<<<grid, 256>>>(x, out);
}

// round 3
// speedup vs baseline: 2.2803x; 2.2803x over previous
#include <cuda_runtime.h>
#include <math_constants.h>

#define NS   5
#define NC   64
#define NB   8
#define HIN  512
#define WIN  512
#define HO   257
#define WO   257
#define NPIX (HO*WO)            // 66049
#define NGRP ((NPIX + 3) / 4)   // 16513 groups of 4 pixels

// Piecewise-linear tables, k-major for conflict-light smem lookups:
//   P[o](L) = max(S1 + S2*L, 0), k = #{sorted thresholds < L}
__device__ float2 g_tab[NS][65][NC];   // [s][k][o]
__device__ float  g_th [NS][64];
__device__ float  g_wv [NS][4];

// ---------------------------------------------------------------------------
// Kernel 1: build tables. 5 blocks x 64 threads. Bitonic sort + smem-staged
// w2; doubles for the running prefix sums (error-free vs reference).
// ---------------------------------------------------------------------------
__global__ void precompute_kernel(
    const float* __restrict__ lp, const float* __restrict__ hp,
    const float* __restrict__ w1, const float* __restrict__ w2,
    const float* __restrict__ g1, const float* __restrict__ b1,
    const float* __restrict__ m1, const float* __restrict__ v1,
    const float* __restrict__ g2, const float* __restrict__ b2,
    const float* __restrict__ m2, const float* __restrict__ v2)
{
    const int s = blockIdx.x;
    const int c = threadIdx.x;      // 0..63

    __shared__ float  sw2[64 * 64];
    __shared__ double sA[64], sB[64];
    __shared__ float  sthv[64];
    __shared__ int    sidx[64];

    for (int i = c; i < 64 * 64; i += 64) sw2[i] = w2[s * 4096 + i];

    {
        double sc1 = (double)g1[s*NC + c] / sqrt((double)v1[s*NC + c] + 1e-5);
        double sh1 = (double)b1[s*NC + c] - (double)m1[s*NC + c] * sc1;
        double A   = (double)w1[s*NC + c] * sc1;
        sA[c] = A; sB[c] = sh1;
        sthv[c] = (A != 0.0) ? (float)(-sh1 / A) : CUDART_INF_F;
        sidx[c] = c;
    }
    __syncthreads();

    // bitonic sort of 64 (key sthv, payload sidx)
    for (int ksz = 2; ksz <= 64; ksz <<= 1) {
        for (int j = ksz >> 1; j > 0; j >>= 1) {
            int ixj = c ^ j;
            if (ixj > c) {
                float a = sthv[c], bb = sthv[ixj];
                int   ia = sidx[c], ib = sidx[ixj];
                bool  up = ((c & ksz) == 0);
                if (up ? (a > bb) : (a < bb)) {
                    sthv[c] = bb; sthv[ixj] = a;
                    sidx[c] = ib; sidx[ixj] = ia;
                }
            }
            __syncthreads();
        }
    }

    g_th[s][c] = sthv[c];
    if (c == 0) {
        g_wv[s][0] = lp[s*2]; g_wv[s][1] = lp[s*2+1];
        g_wv[s][2] = hp[s*2]; g_wv[s][3] = hp[s*2+1];
    }

    // per output channel o = c: sweep k
    double sc2 = (double)g2[s*NC + c] / sqrt((double)v2[s*NC + c] + 1e-5);
    double sh2 = (double)b2[s*NC + c] - (double)m2[s*NC + c] * sc2;

    double s1 = 0.0, s2 = 0.0;
    for (int cc = 0; cc < 64; cc++) {
        double w = (double)sw2[c*64 + cc];
        double a = sA[cc], bb = sB[cc];
        if (a < 0.0)                   { s1 += w*bb; s2 += w*a; }
        else if (a == 0.0 && bb > 0.0) { s1 += w*bb; }
    }
    for (int k = 0; k <= 64; k++) {
        g_tab[s][k][c] = make_float2((float)(sc2*s1 + sh2), (float)(sc2*s2));
        if (k < 64) {
            int cc = sidx[k];
            double w = (double)sw2[c*64 + cc];
            double a = sA[cc], bb = sB[cc];
            if (a > 0.0)      { s1 += w*bb; s2 += w*a; }
            else if (a < 0.0) { s1 -= w*bb; s2 -= w*a; }
        }
    }
}

// ---------------------------------------------------------------------------
// Kernel 2: each thread owns 4 consecutive pixels; writes every plane with
// an aligned STG.128 using a per-plane compile-time shift d = o & 3 and a
// 7-slot (3 halo + 4 own) register window filled via shfl.
// ---------------------------------------------------------------------------
__global__ void __launch_bounds__(256)
dwt_pwl_kernel(const float* __restrict__ x, float* __restrict__ out)
{
    __shared__ float2 stab[65 * 65];   // idx = k*65 + o  (padded stride)
    __shared__ float  sth[64];

    const int sb = blockIdx.y;          // 0..39
    const int s  = sb / NB;
    const int b  = sb - s * NB;

    const float2* gt = &g_tab[s][0][0];
    for (int i = threadIdx.x; i < 65 * 64; i += 256) {
        int k = i >> 6, o = i & 63;
        stab[k * 65 + o] = gt[i];
    }
    if (threadIdx.x < 64) sth[threadIdx.x] = g_th[s][threadIdx.x];
    __syncthreads();

    const float lp0 = g_wv[s][0], lp1 = g_wv[s][1];
    const float hp0 = g_wv[s][2], hp1 = g_wv[s][3];

    const float* __restrict__ xb = x + (size_t)b * HIN * WIN;
    float* __restrict__ outL = out + (size_t)sb * NPIX;
    float* __restrict__ outH = out + (size_t)(NS*NB + sb) * NPIX;
    float* __restrict__ outP = out + (size_t)2*NS*NB*NPIX + (size_t)sb * NC * NPIX;

    const int lane = threadIdx.x & 31;
    const int gstride = gridDim.x * blockDim.x;

    // compute L, Hc, rank k for one pixel (fully guarded, incl. bottom row)
    auto pixLHK = [&](int pix, float& L, float& H, int& k) {
        L = 0.f; H = 0.f;
        if (pix >= 0 && pix < NPIX) {
            unsigned up = (unsigned)pix;
            int i = up / WO;
            int j = up - i * WO;
            int r0 = 2*i - 1, r1 = 2*i;
            int c0 = 2*j - 1, c1 = 2*j;
            float x00 = (r0 >= 0  && c0 >= 0 ) ? xb[r0*WIN + c0] : 0.f;
            float x01 = (r0 >= 0  && c1 < WIN) ? xb[r0*WIN + c1] : 0.f;
            float x10 = (r1 < HIN && c0 >= 0 ) ? xb[r1*WIN + c0] : 0.f;
            float x11 = (r1 < HIN && c1 < WIN) ? xb[r1*WIN + c1] : 0.f;
            L = lp0*(lp0*x00 + lp1*x01) + lp1*(lp0*x10 + lp1*x11);
            H = hp0*(hp0*x00 + hp1*x01) + hp1*(hp0*x10 + hp1*x11);
        }
        int kk = (sth[31]       < L) ? 32 : 0;
        kk += (sth[kk + 15] < L) ? 16 : 0;
        kk += (sth[kk +  7] < L) ?  8 : 0;
        kk += (sth[kk +  3] < L) ?  4 : 0;
        kk += (sth[kk +  1] < L) ?  2 : 0;
        kk += (sth[kk     ] < L) ?  1 : 0;
        k = kk;
    };

    for (int gw = blockIdx.x * 256 + (int)(threadIdx.x & ~31u); gw < NGRP;
         gw += gstride)
    {
        const int g = gw + lane;
        const int pix0 = 4 * g;

        float Ls[7], Hs[7]; int ks[7];
        pixLHK(pix0 + 0, Ls[3], Hs[3], ks[3]);
        pixLHK(pix0 + 1, Ls[4], Hs[4], ks[4]);
        pixLHK(pix0 + 2, Ls[5], Hs[5], ks[5]);
        pixLHK(pix0 + 3, Ls[6], Hs[6], ks[6]);

        // halo (previous group's pixels 1..3) via shfl; lane 0 recomputes
        Ls[0] = __shfl_up_sync(0xffffffffu, Ls[4], 1);
        Ls[1] = __shfl_up_sync(0xffffffffu, Ls[5], 1);
        Ls[2] = __shfl_up_sync(0xffffffffu, Ls[6], 1);
        Hs[0] = __shfl_up_sync(0xffffffffu, Hs[4], 1);
        Hs[1] = __shfl_up_sync(0xffffffffu, Hs[5], 1);
        Hs[2] = __shfl_up_sync(0xffffffffu, Hs[6], 1);
        ks[0] = __shfl_up_sync(0xffffffffu, ks[4], 1);
        ks[1] = __shfl_up_sync(0xffffffffu, ks[5], 1);
        ks[2] = __shfl_up_sync(0xffffffffu, ks[6], 1);
        if (lane == 0) {
            pixLHK(pix0 - 3, Ls[0], Hs[0], ks[0]);
            pixLHK(pix0 - 2, Ls[1], Hs[1], ks[1]);
            pixLHK(pix0 - 1, Ls[2], Hs[2], ks[2]);
        }

        if (g >= NGRP) continue;

        const bool edge = (g == 0) || (g == NGRP - 1);

        if (!edge) {
            // ---- P planes: 16 quads of 4 channels, one STG.128 each ----
            float* bp = outP + pix0;
            #pragma unroll
            for (int q = 0; q < 16; q++) {
                const int o0 = 4 * q;
                {   // o0, d=0: slots 3..6, addr +0
                    float2 f0 = stab[ks[3]*65 + o0], f1 = stab[ks[4]*65 + o0];
                    float2 f2 = stab[ks[5]*65 + o0], f3 = stab[ks[6]*65 + o0];
                    float4 v = make_float4(fmaxf(fmaf(f0.y, Ls[3], f0.x), 0.f),
                                           fmaxf(fmaf(f1.y, Ls[4], f1.x), 0.f),
                                           fmaxf(fmaf(f2.y, Ls[5], f2.x), 0.f),
                                           fmaxf(fmaf(f3.y, Ls[6], f3.x), 0.f));
                    *reinterpret_cast<float4*>(bp) = v;
                }
                {   // o0+1, d=1: slots 2..5, addr +NPIX-1
                    float2 f0 = stab[ks[2]*65 + o0+1], f1 = stab[ks[3]*65 + o0+1];
                    float2 f2 = stab[ks[4]*65 + o0+1], f3 = stab[ks[5]*65 + o0+1];
                    float4 v = make_float4(fmaxf(fmaf(f0.y, Ls[2], f0.x), 0.f),
                                           fmaxf(fmaf(f1.y, Ls[3], f1.x), 0.f),
                                           fmaxf(fmaf(f2.y, Ls[4], f2.x), 0.f),
                                           fmaxf(fmaf(f3.y, Ls[5], f3.x), 0.f));
                    *reinterpret_cast<float4*>(bp + (NPIX - 1)) = v;
                }
                {   // o0+2, d=2: slots 1..4, addr +2*NPIX-2
                    float2 f0 = stab[ks[1]*65 + o0+2], f1 = stab[ks[2]*65 + o0+2];
                    float2 f2 = stab[ks[3]*65 + o0+2], f3 = stab[ks[4]*65 + o0+2];
                    float4 v = make_float4(fmaxf(fmaf(f0.y, Ls[1], f0.x), 0.f),
                                           fmaxf(fmaf(f1.y, Ls[2], f1.x), 0.f),
                                           fmaxf(fmaf(f2.y, Ls[3], f2.x), 0.f),
                                           fmaxf(fmaf(f3.y, Ls[4], f3.x), 0.f));
                    *reinterpret_cast<float4*>(bp + (2*NPIX - 2)) = v;
                }
                {   // o0+3, d=3: slots 0..3, addr +3*NPIX-3
                    float2 f0 = stab[ks[0]*65 + o0+3], f1 = stab[ks[1]*65 + o0+3];
                    float2 f2 = stab[ks[2]*65 + o0+3], f3 = stab[ks[3]*65 + o0+3];
                    float4 v = make_float4(fmaxf(fmaf(f0.y, Ls[0], f0.x), 0.f),
                                           fmaxf(fmaf(f1.y, Ls[1], f1.x), 0.f),
                                           fmaxf(fmaf(f2.y, Ls[2], f2.x), 0.f),
                                           fmaxf(fmaf(f3.y, Ls[3], f3.x), 0.f));
                    *reinterpret_cast<float4*>(bp + (3*NPIX - 3)) = v;
                }
                bp += (size_t)4 * NPIX;
            }

            // ---- L / Hc planes: runtime shift (uniform per block) ----
            switch (sb & 3) {
            case 0:
                *reinterpret_cast<float4*>(outL + pix0) =
                    make_float4(Ls[3], Ls[4], Ls[5], Ls[6]);
                *reinterpret_cast<float4*>(outH + pix0) =
                    make_float4(Hs[3], Hs[4], Hs[5], Hs[6]);
                break;
            case 1:
                *reinterpret_cast<float4*>(outL + pix0 - 1) =
                    make_float4(Ls[2], Ls[3], Ls[4], Ls[5]);
                *reinterpret_cast<float4*>(outH + pix0 - 1) =
                    make_float4(Hs[2], Hs[3], Hs[4], Hs[5]);
                break;
            case 2:
                *reinterpret_cast<float4*>(outL + pix0 - 2) =
                    make_float4(Ls[1], Ls[2], Ls[3], Ls[4]);
                *reinterpret_cast<float4*>(outH + pix0 - 2) =
                    make_float4(Hs[1], Hs[2], Hs[3], Hs[4]);
                break;
            default:
                *reinterpret_cast<float4*>(outL + pix0 - 3) =
                    make_float4(Ls[0], Ls[1], Ls[2], Ls[3]);
                *reinterpret_cast<float4*>(outH + pix0 - 3) =
                    make_float4(Hs[0], Hs[1], Hs[2], Hs[3]);
                break;
            }
        } else {
            // ---- edge groups (first/last of plane): masked scalar stores ----
            #pragma unroll 4
            for (int o = 0; o < 64; o++) {
                const int d = o & 3;
                #pragma unroll
                for (int e = 0; e < 4; e++) {
                    int pix = pix0 - d + e;
                    if (pix >= 0 && pix < NPIX) {
                        float2 f = stab[ks[3 - d + e] * 65 + o];
                        outP[(size_t)o * NPIX + pix] =
                            fmaxf(fmaf(f.y, Ls[3 - d + e], f.x), 0.f);
                    }
                }
            }
            switch (sb & 3) {
            #define EDGE_LH(D)                                              \
                { _Pragma("unroll")                                         \
                  for (int e = 0; e < 4; e++) {                             \
                      int pix = pix0 - (D) + e;                             \
                      if (pix >= 0 && pix < NPIX) {                         \
                          outL[pix] = Ls[3 - (D) + e];                      \
                          outH[pix] = Hs[3 - (D) + e];                      \
                      }                                                     \
                  } }
            case 0:  EDGE_LH(0) break;
            case 1:  EDGE_LH(1) break;
            case 2:  EDGE_LH(2) break;
            default: EDGE_LH(3) break;
            #undef EDGE_LH
            }
        }
    }
}

// ---------------------------------------------------------------------------
extern "C" void kernel_launch(void* const* d_in, const int* in_sizes, int n_in,
                              void* d_out, int out_size)
{
    const float* x  = (const float*)d_in[0];
    const float* lp = (const float*)d_in[1];
    const float* hp = (const float*)d_in[2];
    const float* w1 = (const float*)d_in[3];
    const float* w2 = (const float*)d_in[4];
    const float* g1 = (const float*)d_in[5];
    const float* b1 = (const float*)d_in[6];
    const float* m1 = (const float*)d_in[7];
    const float* v1 = (const float*)d_in[8];
    const float* g2 = (const float*)d_in[9];
    const float* b2 = (const float*)d_in[10];
    const float* m2 = (const float*)d_in[11];
    const float* v2 = (const float*)d_in[12];
    float* out = (float*)d_out;

    precompute_kernel<<<NS, 64>>>(lp, hp, w1, w2, g1, b1, m1, v1,
                                  g2, b2, m2, v2);

    dim3 grid(15, NS * NB);   // 600 blocks: ~1 wave, ~4.3 groups/thread
    dwt_pwl_kernel<<<grid, 256>>>(x, out);
}

// round 4
// speedup vs baseline: 2.3298x; 1.0217x over previous
#include <cuda_runtime.h>
#include <math_constants.h>

#define NS   5
#define NC   64
#define NB   8
#define HIN  512
#define WIN  512
#define HO   257
#define WO   257
#define NPIX (HO*WO)            // 66049
#define NGRP ((NPIX + 3) / 4)   // 16513 groups of 4 pixels

// Split piecewise-linear tables (fp32), k-major:
//   P[o](L) = max(S1[k][o] + S2[k][o]*L, 0), k = #{sorted thresholds < L}
__device__ float  g_tab1[NS][65][NC];
__device__ float  g_tab2[NS][65][NC];
__device__ float  g_th [NS][64];
__device__ float  g_wv [NS][4];
__device__ double g_Ad [NS][64];
__device__ double g_Bd [NS][64];
__device__ int    g_rk [NS][64];

// ---------------------------------------------------------------------------
// Kernel 1a: per-channel meta (A, B, thresholds, ranks). 5 blocks x 64 thr.
// ---------------------------------------------------------------------------
__global__ void precompute_meta(
    const float* __restrict__ lp, const float* __restrict__ hp,
    const float* __restrict__ w1,
    const float* __restrict__ g1, const float* __restrict__ b1,
    const float* __restrict__ m1, const float* __restrict__ v1)
{
    const int s = blockIdx.x;
    const int c = threadIdx.x;      // 0..63

    __shared__ float sthv[64];
    __shared__ int   sidx[64];

    double sc1 = (double)g1[s*NC + c] / sqrt((double)v1[s*NC + c] + 1e-5);
    double sh1 = (double)b1[s*NC + c] - (double)m1[s*NC + c] * sc1;
    double A   = (double)w1[s*NC + c] * sc1;
    g_Ad[s][c] = A;
    g_Bd[s][c] = sh1;
    sthv[c] = (A != 0.0) ? (float)(-sh1 / A) : CUDART_INF_F;
    sidx[c] = c;
    __syncthreads();

    // bitonic sort of 64 (key sthv, payload sidx)
    for (int ksz = 2; ksz <= 64; ksz <<= 1) {
        for (int j = ksz >> 1; j > 0; j >>= 1) {
            int ixj = c ^ j;
            if (ixj > c) {
                float a = sthv[c], bb = sthv[ixj];
                int   ia = sidx[c], ib = sidx[ixj];
                bool  up = ((c & ksz) == 0);
                if (up ? (a > bb) : (a < bb)) {
                    sthv[c] = bb; sthv[ixj] = a;
                    sidx[c] = ib; sidx[ixj] = ia;
                }
            }
            __syncthreads();
        }
    }

    g_th[s][c] = sthv[c];
    g_rk[s][sidx[c]] = c;           // rank of channel sidx[c] is c
    if (c == 0) {
        g_wv[s][0] = lp[s*2]; g_wv[s][1] = lp[s*2+1];
        g_wv[s][2] = hp[s*2]; g_wv[s][3] = hp[s*2+1];
    }
}

// ---------------------------------------------------------------------------
// Kernel 1b: table fill, fully parallel. grid (65, 5) x 64 threads.
// Entry (s, k, o): masked double sum over 64 channels.
// ---------------------------------------------------------------------------
__global__ void precompute_tab(
    const float* __restrict__ w2,
    const float* __restrict__ g2, const float* __restrict__ b2,
    const float* __restrict__ m2, const float* __restrict__ v2)
{
    const int s = blockIdx.y;
    const int k = blockIdx.x;       // 0..64
    const int o = threadIdx.x;      // 0..63

    __shared__ float  sw2[64 * 65];   // padded stride: bank-conflict-free
    __shared__ double sAd[64], sBd[64];
    __shared__ int    srk[64];

    for (int idx = o; idx < 64 * 64; idx += 64)
        sw2[(idx >> 6) * 65 + (idx & 63)] = w2[s * 4096 + idx];
    sAd[o] = g_Ad[s][o];
    sBd[o] = g_Bd[s][o];
    srk[o] = g_rk[s][o];
    __syncthreads();

    double sc2 = (double)g2[s*NC + o] / sqrt((double)v2[s*NC + o] + 1e-5);
    double sh2 = (double)b2[s*NC + o] - (double)m2[s*NC + o] * sc2;

    double s1 = 0.0, s2 = 0.0;
    #pragma unroll 4
    for (int c = 0; c < 64; c++) {
        double a = sAd[c], bb = sBd[c];
        bool act = (a > 0.0) ? (srk[c] < k)
                 : (a < 0.0) ? (srk[c] >= k)
                             : (bb > 0.0);
        if (act) {
            double w = (double)sw2[o*65 + c];
            s1 += w * bb;
            s2 += w * a;
        }
    }
    g_tab1[s][k][o] = (float)(sc2*s1 + sh2);
    g_tab2[s][k][o] = (float)(sc2*s2);
}

// ---------------------------------------------------------------------------
// Kernel 2: main. Thread owns 4 consecutive pixels; STG.128 everywhere via
// per-plane shift d = o & 3 with a 7-slot (3 halo + 4 own) register window.
// ---------------------------------------------------------------------------
__global__ void __launch_bounds__(256, 4)
dwt_pwl_kernel(const float* __restrict__ x, float* __restrict__ out)
{
    __shared__ float s1t[65 * 65];   // idx = k*65 + o ; bank = (k+o)%32
    __shared__ float s2t[65 * 65];
    __shared__ float sth[64];

    const int sb = blockIdx.y;          // 0..39
    const int s  = sb / NB;
    const int b  = sb - s * NB;

    const float* gt1 = &g_tab1[s][0][0];
    const float* gt2 = &g_tab2[s][0][0];
    for (int i = threadIdx.x; i < 65 * 64; i += 256) {
        int k = i >> 6, o = i & 63;
        s1t[k * 65 + o] = gt1[i];
        s2t[k * 65 + o] = gt2[i];
    }
    if (threadIdx.x < 64) sth[threadIdx.x] = g_th[s][threadIdx.x];
    __syncthreads();

    const float lp0 = g_wv[s][0], lp1 = g_wv[s][1];
    const float hp0 = g_wv[s][2], hp1 = g_wv[s][3];

    const float* __restrict__ xb = x + (size_t)b * HIN * WIN;
    float* __restrict__ outL = out + (size_t)sb * NPIX;
    float* __restrict__ outH = out + (size_t)(NS*NB + sb) * NPIX;
    float* __restrict__ outP = out + (size_t)2*NS*NB*NPIX + (size_t)sb * NC * NPIX;

    const int lane = threadIdx.x & 31;
    const int gstride = gridDim.x * blockDim.x;

    auto rankOf = [&](float L) -> int {
        int kk = (sth[31]       < L) ? 32 : 0;
        kk += (sth[kk + 15] < L) ? 16 : 0;
        kk += (sth[kk +  7] < L) ?  8 : 0;
        kk += (sth[kk +  3] < L) ?  4 : 0;
        kk += (sth[kk +  1] < L) ?  2 : 0;
        kk += (sth[kk     ] < L) ?  1 : 0;
        return kk;
    };

    // scalar fallback: L, Hc, rank for one pixel (fully guarded)
    auto pixLHK = [&](int pix, float& L, float& H, int& k) {
        L = 0.f; H = 0.f;
        if (pix >= 0 && pix < NPIX) {
            unsigned up = (unsigned)pix;
            int i = up / WO;
            int j = up - i * WO;
            int r0 = 2*i - 1, r1 = 2*i;
            int c0 = 2*j - 1, c1 = 2*j;
            float x00 = (r0 >= 0  && c0 >= 0 ) ? xb[r0*WIN + c0] : 0.f;
            float x01 = (r0 >= 0  && c1 < WIN) ? xb[r0*WIN + c1] : 0.f;
            float x10 = (r1 < HIN && c0 >= 0 ) ? xb[r1*WIN + c0] : 0.f;
            float x11 = (r1 < HIN && c1 < WIN) ? xb[r1*WIN + c1] : 0.f;
            L = lp0*(lp0*x00 + lp1*x01) + lp1*(lp0*x10 + lp1*x11);
            H = hp0*(hp0*x00 + hp1*x01) + hp1*(hp0*x10 + hp1*x11);
        }
        k = rankOf(L);
    };

    for (int gw = blockIdx.x * 256 + (int)(threadIdx.x & ~31u); gw < NGRP;
         gw += gstride)
    {
        const int g = gw + lane;
        const int pix0 = 4 * g;

        float Ls[7], Hs[7]; int ks[7];

        // ---- own 4 pixels: vectorized fast path (same row, full width) ----
        const int irow = pix0 / WO;
        const int j0   = pix0 - irow * WO;
        if (g < NGRP && j0 <= 252) {
            const int r0 = 2*irow - 1, r1 = 2*irow;
            const bool h0 = (r0 >= 0), h1 = (r1 < HIN);
            const float* p0 = xb + r0 * WIN;
            const float* p1 = xb + r1 * WIN;
            const int cb = 2*j0 - 2;
            float2 t0[5], t1[5];
            #pragma unroll
            for (int e = 0; e < 5; e++) {
                const int cc = cb + 2*e;
                const bool okc = (cc >= 0);
                t0[e] = (h0 && okc) ? *reinterpret_cast<const float2*>(p0 + cc)
                                    : make_float2(0.f, 0.f);
                t1[e] = (h1 && okc) ? *reinterpret_cast<const float2*>(p1 + cc)
                                    : make_float2(0.f, 0.f);
            }
            #pragma unroll
            for (int e = 0; e < 4; e++) {
                const float x00 = t0[e].y, x01 = t0[e+1].x;
                const float x10 = t1[e].y, x11 = t1[e+1].x;
                Ls[3+e] = lp0*(lp0*x00 + lp1*x01) + lp1*(lp0*x10 + lp1*x11);
                Hs[3+e] = hp0*(hp0*x00 + hp1*x01) + hp1*(hp0*x10 + hp1*x11);
                ks[3+e] = rankOf(Ls[3+e]);
            }
        } else {
            pixLHK(pix0 + 0, Ls[3], Hs[3], ks[3]);
            pixLHK(pix0 + 1, Ls[4], Hs[4], ks[4]);
            pixLHK(pix0 + 2, Ls[5], Hs[5], ks[5]);
            pixLHK(pix0 + 3, Ls[6], Hs[6], ks[6]);
        }

        // halo (previous group's pixels 1..3) via shfl; lane 0 recomputes
        Ls[0] = __shfl_up_sync(0xffffffffu, Ls[4], 1);
        Ls[1] = __shfl_up_sync(0xffffffffu, Ls[5], 1);
        Ls[2] = __shfl_up_sync(0xffffffffu, Ls[6], 1);
        Hs[0] = __shfl_up_sync(0xffffffffu, Hs[4], 1);
        Hs[1] = __shfl_up_sync(0xffffffffu, Hs[5], 1);
        Hs[2] = __shfl_up_sync(0xffffffffu, Hs[6], 1);
        ks[0] = __shfl_up_sync(0xffffffffu, ks[4], 1);
        ks[1] = __shfl_up_sync(0xffffffffu, ks[5], 1);
        ks[2] = __shfl_up_sync(0xffffffffu, ks[6], 1);
        if (lane == 0) {
            pixLHK(pix0 - 3, Ls[0], Hs[0], ks[0]);
            pixLHK(pix0 - 2, Ls[1], Hs[1], ks[1]);
            pixLHK(pix0 - 1, Ls[2], Hs[2], ks[2]);
        }

        if (g >= NGRP) continue;

        const bool edge = (g == 0) || (g == NGRP - 1);

        if (!edge) {
            // ---- P planes: 16 quads of 4 channels, one STG.128 each ----
            float* bp = outP + pix0;
            #pragma unroll
            for (int q = 0; q < 16; q++) {
                const int o0 = 4 * q;
                #define PWL(slot, oo) \
                    fmaxf(fmaf(s2t[ks[slot]*65 + (oo)], Ls[slot], \
                               s1t[ks[slot]*65 + (oo)]), 0.f)
                {   // o0, d=0: slots 3..6
                    float4 v = make_float4(PWL(3, o0), PWL(4, o0),
                                           PWL(5, o0), PWL(6, o0));
                    *reinterpret_cast<float4*>(bp) = v;
                }
                {   // o0+1, d=1: slots 2..5
                    float4 v = make_float4(PWL(2, o0+1), PWL(3, o0+1),
                                           PWL(4, o0+1), PWL(5, o0+1));
                    *reinterpret_cast<float4*>(bp + (NPIX - 1)) = v;
                }
                {   // o0+2, d=2: slots 1..4
                    float4 v = make_float4(PWL(1, o0+2), PWL(2, o0+2),
                                           PWL(3, o0+2), PWL(4, o0+2));
                    *reinterpret_cast<float4*>(bp + (2*NPIX - 2)) = v;
                }
                {   // o0+3, d=3: slots 0..3
                    float4 v = make_float4(PWL(0, o0+3), PWL(1, o0+3),
                                           PWL(2, o0+3), PWL(3, o0+3));
                    *reinterpret_cast<float4*>(bp + (3*NPIX - 3)) = v;
                }
                #undef PWL
                bp += (size_t)4 * NPIX;
            }

            // ---- L / Hc planes: runtime shift (uniform per block) ----
            switch (sb & 3) {
            case 0:
                *reinterpret_cast<float4*>(outL + pix0) =
                    make_float4(Ls[3], Ls[4], Ls[5], Ls[6]);
                *reinterpret_cast<float4*>(outH + pix0) =
                    make_float4(Hs[3], Hs[4], Hs[5], Hs[6]);
                break;
            case 1:
                *reinterpret_cast<float4*>(outL + pix0 - 1) =
                    make_float4(Ls[2], Ls[3], Ls[4], Ls[5]);
                *reinterpret_cast<float4*>(outH + pix0 - 1) =
                    make_float4(Hs[2], Hs[3], Hs[4], Hs[5]);
                break;
            case 2:
                *reinterpret_cast<float4*>(outL + pix0 - 2) =
                    make_float4(Ls[1], Ls[2], Ls[3], Ls[4]);
                *reinterpret_cast<float4*>(outH + pix0 - 2) =
                    make_float4(Hs[1], Hs[2], Hs[3], Hs[4]);
                break;
            default:
                *reinterpret_cast<float4*>(outL + pix0 - 3) =
                    make_float4(Ls[0], Ls[1], Ls[2], Ls[3]);
                *reinterpret_cast<float4*>(outH + pix0 - 3) =
                    make_float4(Hs[0], Hs[1], Hs[2], Hs[3]);
                break;
            }
        } else {
            // ---- edge groups (first/last of plane): masked scalar stores ----
            #pragma unroll 4
            for (int o = 0; o < 64; o++) {
                const int d = o & 3;
                #pragma unroll
                for (int e = 0; e < 4; e++) {
                    int pix = pix0 - d + e;
                    if (pix >= 0 && pix < NPIX) {
                        const int sl = 3 - d + e;
                        outP[(size_t)o * NPIX + pix] =
                            fmaxf(fmaf(s2t[ks[sl]*65 + o], Ls[sl],
                                       s1t[ks[sl]*65 + o]), 0.f);
                    }
                }
            }
            switch (sb & 3) {
            #define EDGE_LH(D)                                              \
                { _Pragma("unroll")                                         \
                  for (int e = 0; e < 4; e++) {                             \
                      int pix = pix0 - (D) + e;                             \
                      if (pix >= 0 && pix < NPIX) {                         \
                          outL[pix] = Ls[3 - (D) + e];                      \
                          outH[pix] = Hs[3 - (D) + e];                      \
                      }                                                     \
                  } }
            case 0:  EDGE_LH(0) break;
            case 1:  EDGE_LH(1) break;
            case 2:  EDGE_LH(2) break;
            default: EDGE_LH(3) break;
            #undef EDGE_LH
            }
        }
    }
}

// ---------------------------------------------------------------------------
extern "C" void kernel_launch(void* const* d_in, const int* in_sizes, int n_in,
                              void* d_out, int out_size)
{
    const float* x  = (const float*)d_in[0];
    const float* lp = (const float*)d_in[1];
    const float* hp = (const float*)d_in[2];
    const float* w1 = (const float*)d_in[3];
    const float* w2 = (const float*)d_in[4];
    const float* g1 = (const float*)d_in[5];
    const float* b1 = (const float*)d_in[6];
    const float* m1 = (const float*)d_in[7];
    const float* v1 = (const float*)d_in[8];
    const float* g2 = (const float*)d_in[9];
    const float* b2 = (const float*)d_in[10];
    const float* m2 = (const float*)d_in[11];
    const float* v2 = (const float*)d_in[12];
    float* out = (float*)d_out;

    precompute_meta<<<NS, 64>>>(lp, hp, w1, g1, b1, m1, v1);
    precompute_tab<<<dim3(65, NS), 64>>>(w2, g2, b2, m2, v2);

    dim3 grid(15, NS * NB);   // 600 blocks
    dwt_pwl_kernel<<<grid, 256>>>(x, out);
}